// round 3
// baseline (speedup 1.0000x reference)
#include <cuda_runtime.h>
#include <math.h>

#define NN 32768     // total nodes
#define NE 524288    // total edges
#define H 64         // hidden
#define H2 128       // 2*hidden
#define NBATCH 16
#define NS 2048      // nodes per graph
#define NL 4
#define NY 64
#define TE 64        // rows per GEMM tile
#define TEP 68       // padded tile stride
#define EPSN 1e-5f

__device__ float g_h[NN * H];
__device__ float g_agg[NN * H];
__device__ float g_u[NN * H];
__device__ float g_stats[NBATCH * H * 2];
__device__ float g_X[NN * 3];
__device__ float g_Y[NY * 3];
__device__ double g_acc[3];

// -------------------- encoder: h = x @ enc_W + enc_b --------------------
__global__ void k_encode(const float* __restrict__ x, const float* __restrict__ W,
                         const float* __restrict__ b) {
    int idx = blockIdx.x * blockDim.x + threadIdx.x;
    int n = idx >> 6, c = idx & 63;
    float x0 = x[n * 3 + 0], x1 = x[n * 3 + 1], x2 = x[n * 3 + 2];
    g_h[idx] = fmaf(x0, W[c], fmaf(x1, W[H + c], fmaf(x2, W[2 * H + c], b[c])));
}

// -------------------- fused 2-layer MLP tile kernel --------------------
// MODE 0: edge message MLP. A-rows = [h[dst] ; h[src]], epilogue = atomic scatter to g_agg.
// MODE 1: node update MLP.  A-rows = [h[n] ; agg[n]],   epilogue = store g_u + instance-norm stats.
template <int MODE>
__global__ void __launch_bounds__(256, 2)
k_mlp(const int* __restrict__ esrc, const int* __restrict__ edst,
      const float* __restrict__ W1, const float* __restrict__ b1,
      const float* __restrict__ W2, const float* __restrict__ b2) {
    extern __shared__ float sm[];
    float* sW1 = sm;                  // [128][64]
    float* sW2 = sW1 + H2 * H;        // [64][64]
    float* sA  = sW2 + H * H;         // [128][TEP]  (input, transposed)
    float* sT  = sA + H2 * TEP;       // [64][TEP]   (hidden, transposed)
    float* sb1 = sT + H * TEP;
    float* sb2 = sb1 + H;
    int*   sDst = (int*)(sb2 + H);

    const int tid = threadIdx.x;
    const int e0 = blockIdx.x * TE;

    {   // stage weights
        const float4* g1 = (const float4*)W1;
        float4* d1 = (float4*)sW1;
#pragma unroll
        for (int t = 0; t < 8; ++t) d1[tid + t * 256] = g1[tid + t * 256];
        const float4* g2 = (const float4*)W2;
        float4* d2 = (float4*)sW2;
#pragma unroll
        for (int t = 0; t < 4; ++t) d2[tid + t * 256] = g2[tid + t * 256];
    }
    if (tid < H) { sb1[tid] = b1[tid]; sb2[tid] = b2[tid]; }
    if (MODE == 0 && tid < TE) sDst[tid] = edst[e0 + tid];

    {   // gather: 4 threads per row, transposed store into sA
        int e = tid >> 2, p = tid & 3;
        const float4 *r0, *r1;
        if (MODE == 0) {
            int rd = edst[e0 + e], rs = esrc[e0 + e];
            r0 = (const float4*)(g_h + rd * H);   // xi = h[dst]
            r1 = (const float4*)(g_h + rs * H);   // xj = h[src]
        } else {
            int n = e0 + e;
            r0 = (const float4*)(g_h + n * H);
            r1 = (const float4*)(g_agg + n * H);
        }
#pragma unroll
        for (int q = 0; q < 4; ++q) {
            float4 v = r0[p * 4 + q];
            int k = p * 16 + q * 4;
            sA[(k + 0) * TEP + e] = v.x; sA[(k + 1) * TEP + e] = v.y;
            sA[(k + 2) * TEP + e] = v.z; sA[(k + 3) * TEP + e] = v.w;
            float4 w = r1[p * 4 + q];
            sA[(k + 64) * TEP + e] = w.x; sA[(k + 65) * TEP + e] = w.y;
            sA[(k + 66) * TEP + e] = w.z; sA[(k + 67) * TEP + e] = w.w;
        }
    }
    __syncthreads();

    const int tx = tid & 15, ty = tid >> 4;
    float acc[4][4];
#pragma unroll
    for (int i = 0; i < 4; i++)
#pragma unroll
        for (int j = 0; j < 4; j++) acc[i][j] = 0.f;

#pragma unroll 4
    for (int k = 0; k < H2; ++k) {
        float4 a = *(const float4*)(sA + k * TEP + ty * 4);
        float4 w = *(const float4*)(sW1 + k * H + tx * 4);
        float av[4] = {a.x, a.y, a.z, a.w};
        float wv[4] = {w.x, w.y, w.z, w.w};
#pragma unroll
        for (int i = 0; i < 4; i++)
#pragma unroll
            for (int j = 0; j < 4; j++) acc[i][j] = fmaf(av[i], wv[j], acc[i][j]);
    }
    // bias + relu -> sT (transposed)
#pragma unroll
    for (int j = 0; j < 4; j++) {
        float bb = sb1[tx * 4 + j];
#pragma unroll
        for (int i = 0; i < 4; i++) {
            sT[(tx * 4 + j) * TEP + ty * 4 + i] = fmaxf(acc[i][j] + bb, 0.f);
        }
    }
    __syncthreads();

    float acc2[4][4];
#pragma unroll
    for (int i = 0; i < 4; i++)
#pragma unroll
        for (int j = 0; j < 4; j++) acc2[i][j] = 0.f;

#pragma unroll 4
    for (int k = 0; k < H; ++k) {
        float4 a = *(const float4*)(sT + k * TEP + ty * 4);
        float4 w = *(const float4*)(sW2 + k * H + tx * 4);
        float av[4] = {a.x, a.y, a.z, a.w};
        float wv[4] = {w.x, w.y, w.z, w.w};
#pragma unroll
        for (int i = 0; i < 4; i++)
#pragma unroll
            for (int j = 0; j < 4; j++) acc2[i][j] = fmaf(av[i], wv[j], acc2[i][j]);
    }

    float bb0 = sb2[tx * 4 + 0], bb1 = sb2[tx * 4 + 1];
    float bb2v = sb2[tx * 4 + 2], bb3 = sb2[tx * 4 + 3];

    if (MODE == 0) {
#pragma unroll
        for (int i = 0; i < 4; i++) {
            int d = sDst[ty * 4 + i];
            float4 v = make_float4(fmaxf(acc2[i][0] + bb0, 0.f),
                                   fmaxf(acc2[i][1] + bb1, 0.f),
                                   fmaxf(acc2[i][2] + bb2v, 0.f),
                                   fmaxf(acc2[i][3] + bb3, 0.f));
            atomicAdd(reinterpret_cast<float4*>(g_agg + d * H + tx * 4), v);
        }
    } else {
        float s[4] = {0, 0, 0, 0}, ss[4] = {0, 0, 0, 0};
#pragma unroll
        for (int i = 0; i < 4; i++) {
            int n = e0 + ty * 4 + i;
            float4 v = make_float4(fmaxf(acc2[i][0] + bb0, 0.f),
                                   fmaxf(acc2[i][1] + bb1, 0.f),
                                   fmaxf(acc2[i][2] + bb2v, 0.f),
                                   fmaxf(acc2[i][3] + bb3, 0.f));
            *reinterpret_cast<float4*>(g_u + n * H + tx * 4) = v;
            s[0] += v.x; ss[0] += v.x * v.x;
            s[1] += v.y; ss[1] += v.y * v.y;
            s[2] += v.z; ss[2] += v.z * v.z;
            s[3] += v.w; ss[3] += v.w * v.w;
        }
        __syncthreads();
        float* sRed = sA;  // reuse: [16][64] sums, then [16][64] sumsq
#pragma unroll
        for (int j = 0; j < 4; j++) {
            sRed[ty * 64 + tx * 4 + j] = s[j];
            sRed[1024 + ty * 64 + tx * 4 + j] = ss[j];
        }
        __syncthreads();
        if (tid < H) {
            float a = 0.f, b = 0.f;
#pragma unroll
            for (int r = 0; r < 16; r++) {
                a += sRed[r * 64 + tid];
                b += sRed[1024 + r * 64 + tid];
            }
            int bat = e0 / NS;
            atomicAdd(&g_stats[(bat * H + tid) * 2 + 0], a);
            atomicAdd(&g_stats[(bat * H + tid) * 2 + 1], b);
        }
    }
}

// -------------------- InstanceNorm apply --------------------
__global__ void k_norm() {
    int idx = blockIdx.x * blockDim.x + threadIdx.x;
    int n = idx >> 6, c = idx & 63;
    int b = n >> 11;  // n / NS
    float s = g_stats[(b * H + c) * 2 + 0];
    float ss = g_stats[(b * H + c) * 2 + 1];
    float mean = s * (1.f / NS);
    float var = ss * (1.f / NS) - mean * mean;
    g_h[idx] = (g_u[idx] - mean) * rsqrtf(var + EPSN);
}

// -------------------- decoder + normalize --------------------
__global__ void k_decode(const float* __restrict__ W, const float* __restrict__ b,
                         float* __restrict__ out) {
    __shared__ float sW[H * 3];
    __shared__ float sb[3];
    int tid = threadIdx.x;
    if (tid < H * 3) sW[tid] = W[tid];
    if (tid < 3) sb[tid] = b[tid];
    __syncthreads();
    int n = blockIdx.x * blockDim.x + tid;
    const float4* hr = (const float4*)(g_h + n * H);
    float a0 = sb[0], a1 = sb[1], a2 = sb[2];
#pragma unroll
    for (int k4 = 0; k4 < 16; k4++) {
        float4 v = hr[k4];
        int k = k4 * 4;
        a0 = fmaf(v.x, sW[(k + 0) * 3 + 0], a0); a1 = fmaf(v.x, sW[(k + 0) * 3 + 1], a1); a2 = fmaf(v.x, sW[(k + 0) * 3 + 2], a2);
        a0 = fmaf(v.y, sW[(k + 1) * 3 + 0], a0); a1 = fmaf(v.y, sW[(k + 1) * 3 + 1], a1); a2 = fmaf(v.y, sW[(k + 1) * 3 + 2], a2);
        a0 = fmaf(v.z, sW[(k + 2) * 3 + 0], a0); a1 = fmaf(v.z, sW[(k + 2) * 3 + 1], a1); a2 = fmaf(v.z, sW[(k + 2) * 3 + 2], a2);
        a0 = fmaf(v.w, sW[(k + 3) * 3 + 0], a0); a1 = fmaf(v.w, sW[(k + 3) * 3 + 1], a1); a2 = fmaf(v.w, sW[(k + 3) * 3 + 2], a2);
    }
    float inv = rsqrtf(a0 * a0 + a1 * a1 + a2 * a2);
    a0 *= inv; a1 *= inv; a2 *= inv;
    g_X[n * 3 + 0] = a0; g_X[n * 3 + 1] = a1; g_X[n * 3 + 2] = a2;
    out[n * 3 + 0] = a0; out[n * 3 + 1] = a1; out[n * 3 + 2] = a2;
}

// -------------------- fibonacci sphere + kYY --------------------
__global__ void k_fib_kyy() {
    __shared__ float sY[NY * 3];
    __shared__ float wsum[2];
    int i = threadIdx.x;  // 64 threads
    double phi = 3.14159265358979323846 * (3.0 - sqrt(5.0));
    double y = 1.0 - 2.0 * (double)i / 63.0;
    double r = sqrt(fmax(0.0, 1.0 - y * y));
    double th = phi * (double)i;
    float Yx = (float)(cos(th) * r), Yy = (float)y, Yz = (float)(sin(th) * r);
    sY[i * 3 + 0] = Yx; sY[i * 3 + 1] = Yy; sY[i * 3 + 2] = Yz;
    g_Y[i * 3 + 0] = Yx; g_Y[i * 3 + 1] = Yy; g_Y[i * 3 + 2] = Yz;
    __syncthreads();
    float acc = 0.f;
    for (int j = 0; j < NY; j++) {
        float d = Yx * sY[j * 3] + Yy * sY[j * 3 + 1] + Yz * sY[j * 3 + 2];
        acc += __expf(fmaf(2.f, d, -2.f));
    }
    for (int o = 16; o > 0; o >>= 1) acc += __shfl_down_sync(0xffffffffu, acc, o);
    if ((i & 31) == 0) wsum[i >> 5] = acc;
    __syncthreads();
    if (i == 0) g_acc[2] = ((double)wsum[0] + (double)wsum[1]) / (64.0 * 64.0);
}

// -------------------- kXY --------------------
__global__ void k_kxy() {
    __shared__ float sY[NY * 3];
    int tid = threadIdx.x;
    if (tid < NY * 3) sY[tid] = g_Y[tid];
    __syncthreads();
    int n = blockIdx.x * blockDim.x + tid;
    float x0 = g_X[n * 3], x1 = g_X[n * 3 + 1], x2 = g_X[n * 3 + 2];
    float acc = 0.f;
#pragma unroll 4
    for (int j = 0; j < NY; j++) {
        float d = fmaf(x0, sY[j * 3], fmaf(x1, sY[j * 3 + 1], x2 * sY[j * 3 + 2]));
        acc += __expf(fmaf(2.f, d, -2.f));
    }
    for (int o = 16; o > 0; o >>= 1) acc += __shfl_down_sync(0xffffffffu, acc, o);
    if ((tid & 31) == 0) atomicAdd(&g_acc[1], (double)acc);
}

// -------------------- kXX --------------------
__global__ void __launch_bounds__(128) k_kxx() {
    __shared__ float sx[NS], sy[NS], sz[NS];
    int b = blockIdx.x, tid = threadIdx.x;
    const float* Xb = g_X + b * NS * 3;
    for (int t = tid; t < NS; t += 128) {
        sx[t] = Xb[t * 3]; sy[t] = Xb[t * 3 + 1]; sz[t] = Xb[t * 3 + 2];
    }
    __syncthreads();
    int row = blockIdx.y * 128 + tid;
    float x0 = sx[row], x1 = sy[row], x2 = sz[row];
    float acc = 0.f;
#pragma unroll 4
    for (int j = 0; j < NS; j++) {
        float d = fmaf(x0, sx[j], fmaf(x1, sy[j], x2 * sz[j]));
        acc += __expf(fmaf(2.f, d, -2.f));
    }
    for (int o = 16; o > 0; o >>= 1) acc += __shfl_down_sync(0xffffffffu, acc, o);
    if ((tid & 31) == 0) atomicAdd(&g_acc[0], (double)acc);
}

// -------------------- finalize loss --------------------
__global__ void k_final(float* out, int writeLoss) {
    double loss = g_acc[0] / ((double)NBATCH * NS * NS)
                - 2.0 * g_acc[1] / ((double)NBATCH * NS * NY)
                + g_acc[2];
    if (writeLoss) out[0] = (float)loss;
}

// -------------------- host launch --------------------
extern "C" void kernel_launch(void* const* d_in, const int* in_sizes, int n_in,
                              void* d_out, int out_size) {
    const float* x    = (const float*)d_in[0];
    const int*   esrc = (const int*)d_in[1];
    const int*   edst = (const int*)d_in[2];
    // nbatch may or may not appear as input 3 (scalar). Detect by size.
    int o = (in_sizes[3] == 1) ? 4 : 3;
    const float* encW = (const float*)d_in[o + 0];
    const float* encb = (const float*)d_in[o + 1];
    const float* m1W  = (const float*)d_in[o + 2];
    const float* m1b  = (const float*)d_in[o + 3];
    const float* m2W  = (const float*)d_in[o + 4];
    const float* m2b  = (const float*)d_in[o + 5];
    const float* u1W  = (const float*)d_in[o + 6];
    const float* u1b  = (const float*)d_in[o + 7];
    const float* u2W  = (const float*)d_in[o + 8];
    const float* u2b  = (const float*)d_in[o + 9];
    const float* decW = (const float*)d_in[o + 10];
    const float* decb = (const float*)d_in[o + 11];
    float* out = (float*)d_out;
    int base = (out_size >= NN * 3 + 1) ? 1 : 0;

    size_t SMEM = (size_t)(H2 * H + H * H + H2 * TEP + H * TEP + 2 * H) * sizeof(float)
                + TE * sizeof(int);
    cudaFuncSetAttribute(k_mlp<0>, cudaFuncAttributeMaxDynamicSharedMemorySize, (int)SMEM);
    cudaFuncSetAttribute(k_mlp<1>, cudaFuncAttributeMaxDynamicSharedMemorySize, (int)SMEM);

    void *p_agg, *p_stats, *p_acc;
    cudaGetSymbolAddress(&p_agg, g_agg);
    cudaGetSymbolAddress(&p_stats, g_stats);
    cudaGetSymbolAddress(&p_acc, g_acc);

    k_encode<<<NN * H / 256, 256>>>(x, encW, encb);

    for (int l = 0; l < NL; l++) {
        cudaMemsetAsync(p_agg, 0, (size_t)NN * H * sizeof(float));
        k_mlp<0><<<NE / TE, 256, SMEM>>>(esrc, edst,
                                         m1W + l * H2 * H, m1b + l * H,
                                         m2W + l * H * H, m2b + l * H);
        cudaMemsetAsync(p_stats, 0, (size_t)NBATCH * H * 2 * sizeof(float));
        k_mlp<1><<<NN / TE, 256, SMEM>>>(nullptr, nullptr,
                                         u1W + l * H2 * H, u1b + l * H,
                                         u2W + l * H * H, u2b + l * H);
        k_norm<<<NN * H / 256, 256>>>();
    }

    k_decode<<<NN / 256, 256>>>(decW, decb, out + base);

    cudaMemsetAsync(p_acc, 0, 3 * sizeof(double));
    k_fib_kyy<<<1, 64>>>();
    k_kxy<<<NN / 256, 256>>>();
    dim3 gxx(NBATCH, NS / 128);
    k_kxx<<<gxx, 128>>>();
    k_final<<<1, 1>>>(out, base);
}

// round 4
// speedup vs baseline: 1.0818x; 1.0818x over previous
#include <cuda_runtime.h>
#include <math.h>

#define NN 32768     // total nodes
#define NE 524288    // total edges
#define H 64         // hidden
#define H2 128       // 2*hidden
#define NBATCH 16
#define NS 2048      // nodes per graph
#define NL 4
#define NY 64
#define TE 64        // rows per GEMM tile
#define TEP 68       // padded tile stride
#define EPSN 1e-5f
#define GRID_MLP 296

typedef unsigned long long u64;

__device__ float g_h[NN * H];
__device__ float g_agg[NN * H];
__device__ float g_u[NN * H];
__device__ float g_stats[NBATCH * H * 2];
__device__ float g_X[NN * 3];
__device__ float g_Y[NY * 3];
__device__ double g_acc[3];

// ---- packed fp32x2 helpers (sm_100+ FFMA2) ----
__device__ __forceinline__ u64 fma2(u64 a, u64 b, u64 c) {
    u64 d;
    asm("fma.rn.f32x2 %0, %1, %2, %3;" : "=l"(d) : "l"(a), "l"(b), "l"(c));
    return d;
}
__device__ __forceinline__ u64 dup2(float w) {
    u64 d;
    asm("mov.b64 %0, {%1, %1};" : "=l"(d) : "f"(w));
    return d;
}
__device__ __forceinline__ float2 unpack2(u64 u) {
    float2 f;
    asm("mov.b64 {%0, %1}, %2;" : "=f"(f.x), "=f"(f.y) : "l"(u));
    return f;
}

// -------------------- encoder: h = x @ enc_W + enc_b --------------------
__global__ void k_encode(const float* __restrict__ x, const float* __restrict__ W,
                         const float* __restrict__ b) {
    int idx = blockIdx.x * blockDim.x + threadIdx.x;
    int n = idx >> 6, c = idx & 63;
    float x0 = x[n * 3 + 0], x1 = x[n * 3 + 1], x2 = x[n * 3 + 2];
    g_h[idx] = fmaf(x0, W[c], fmaf(x1, W[H + c], fmaf(x2, W[2 * H + c], b[c])));
}

// -------------------- fused 2-layer MLP, persistent tile loop --------------------
// MODE 0: edge MLP, rows = [h[dst]; h[src]], epilogue scatter-add to g_agg.
// MODE 1: node MLP, rows = [h[n]; agg[n]], epilogue store g_u + IN stats.
template <int MODE>
__global__ void __launch_bounds__(256, 2)
k_mlp(const int* __restrict__ esrc, const int* __restrict__ edst,
      const float* __restrict__ W1, const float* __restrict__ b1,
      const float* __restrict__ W2, const float* __restrict__ b2) {
    extern __shared__ float sm[];
    float* sW1 = sm;                  // [128][64]
    float* sW2 = sW1 + H2 * H;        // [64][64]
    float* sA  = sW2 + H * H;         // [128][TEP]  input, transposed (k-major)
    float* sT  = sA + H2 * TEP;       // [64][TEP]   hidden, transposed
    int*   sDst = (int*)(sT + H * TEP);

    const int tid = threadIdx.x;
    const int tx = tid & 15, ty = tid >> 4;

    {   // stage weights once per block
        const float4* g1 = (const float4*)W1;
        float4* d1 = (float4*)sW1;
#pragma unroll
        for (int t = 0; t < 8; ++t) d1[tid + t * 256] = g1[tid + t * 256];
        const float4* g2 = (const float4*)W2;
        float4* d2 = (float4*)sW2;
#pragma unroll
        for (int t = 0; t < 4; ++t) d2[tid + t * 256] = g2[tid + t * 256];
    }
    float bia1[4], bia2[4];
#pragma unroll
    for (int j = 0; j < 4; j++) { bia1[j] = b1[tx * 4 + j]; bia2[j] = b2[tx * 4 + j]; }

    const int ntiles = (MODE == 0) ? (NE / TE) : (NN / TE);

    for (int tile = blockIdx.x; tile < ntiles; tile += gridDim.x) {
        const int e0 = tile * TE;
        __syncthreads();   // protect smem reuse across iterations / weight staging

        if (MODE == 0 && tid < TE) sDst[tid] = edst[e0 + tid];

        {   // gather: 4 threads per row, transposed store
            int e = tid >> 2, p = tid & 3;
            const float4 *r0, *r1;
            if (MODE == 0) {
                int rd = edst[e0 + e], rs = esrc[e0 + e];
                r0 = (const float4*)(g_h + rd * H);
                r1 = (const float4*)(g_h + rs * H);
            } else {
                int n = e0 + e;
                r0 = (const float4*)(g_h + n * H);
                r1 = (const float4*)(g_agg + n * H);
            }
#pragma unroll
            for (int q = 0; q < 4; ++q) {
                float4 v = r0[p * 4 + q];
                int k = p * 16 + q * 4;
                sA[(k + 0) * TEP + e] = v.x; sA[(k + 1) * TEP + e] = v.y;
                sA[(k + 2) * TEP + e] = v.z; sA[(k + 3) * TEP + e] = v.w;
                float4 w = r1[p * 4 + q];
                sA[(k + 64) * TEP + e] = w.x; sA[(k + 65) * TEP + e] = w.y;
                sA[(k + 66) * TEP + e] = w.z; sA[(k + 67) * TEP + e] = w.w;
            }
        }
        __syncthreads();

        // ---- GEMM1: [TE,128] x [128,64], packed rows ----
        u64 acc[2][4];
#pragma unroll
        for (int p = 0; p < 2; p++)
#pragma unroll
            for (int j = 0; j < 4; j++) acc[p][j] = 0ull;

#pragma unroll 8
        for (int k = 0; k < H2; ++k) {
            const u64* ap = (const u64*)(sA + k * TEP + ty * 4);
            u64 a01 = ap[0], a23 = ap[1];
            float4 w4 = *(const float4*)(sW1 + k * H + tx * 4);
            u64 w0 = dup2(w4.x), w1 = dup2(w4.y), w2 = dup2(w4.z), w3 = dup2(w4.w);
            acc[0][0] = fma2(a01, w0, acc[0][0]); acc[1][0] = fma2(a23, w0, acc[1][0]);
            acc[0][1] = fma2(a01, w1, acc[0][1]); acc[1][1] = fma2(a23, w1, acc[1][1]);
            acc[0][2] = fma2(a01, w2, acc[0][2]); acc[1][2] = fma2(a23, w2, acc[1][2]);
            acc[0][3] = fma2(a01, w3, acc[0][3]); acc[1][3] = fma2(a23, w3, acc[1][3]);
        }
        // bias + relu -> sT (transposed)
#pragma unroll
        for (int j = 0; j < 4; j++) {
            float bb = bia1[j];
            float2 f0 = unpack2(acc[0][j]);
            float2 f1 = unpack2(acc[1][j]);
            float* dst = sT + (tx * 4 + j) * TEP + ty * 4;
            *(float2*)(dst)     = make_float2(fmaxf(f0.x + bb, 0.f), fmaxf(f0.y + bb, 0.f));
            *(float2*)(dst + 2) = make_float2(fmaxf(f1.x + bb, 0.f), fmaxf(f1.y + bb, 0.f));
        }
        __syncthreads();

        // ---- GEMM2: [TE,64] x [64,64], packed rows ----
        u64 acc2[2][4];
#pragma unroll
        for (int p = 0; p < 2; p++)
#pragma unroll
            for (int j = 0; j < 4; j++) acc2[p][j] = 0ull;

#pragma unroll 8
        for (int k = 0; k < H; ++k) {
            const u64* ap = (const u64*)(sT + k * TEP + ty * 4);
            u64 a01 = ap[0], a23 = ap[1];
            float4 w4 = *(const float4*)(sW2 + k * H + tx * 4);
            u64 w0 = dup2(w4.x), w1 = dup2(w4.y), w2 = dup2(w4.z), w3 = dup2(w4.w);
            acc2[0][0] = fma2(a01, w0, acc2[0][0]); acc2[1][0] = fma2(a23, w0, acc2[1][0]);
            acc2[0][1] = fma2(a01, w1, acc2[0][1]); acc2[1][1] = fma2(a23, w1, acc2[1][1]);
            acc2[0][2] = fma2(a01, w2, acc2[0][2]); acc2[1][2] = fma2(a23, w2, acc2[1][2]);
            acc2[0][3] = fma2(a01, w3, acc2[0][3]); acc2[1][3] = fma2(a23, w3, acc2[1][3]);
        }

        // unpack: vout[i][j], i = local row (ty*4+i), j = col (tx*4+j)
        float vout[4][4];
#pragma unroll
        for (int p = 0; p < 2; p++)
#pragma unroll
            for (int j = 0; j < 4; j++) {
                float bb = bia2[j];
                float2 f = unpack2(acc2[p][j]);
                vout[2 * p + 0][j] = fmaxf(f.x + bb, 0.f);
                vout[2 * p + 1][j] = fmaxf(f.y + bb, 0.f);
            }

        if (MODE == 0) {
#pragma unroll
            for (int i = 0; i < 4; i++) {
                int d = sDst[ty * 4 + i];
                float4 v = make_float4(vout[i][0], vout[i][1], vout[i][2], vout[i][3]);
                atomicAdd(reinterpret_cast<float4*>(g_agg + d * H + tx * 4), v);
            }
        } else {
            float s[4] = {0, 0, 0, 0}, ss[4] = {0, 0, 0, 0};
#pragma unroll
            for (int i = 0; i < 4; i++) {
                int n = e0 + ty * 4 + i;
                float4 v = make_float4(vout[i][0], vout[i][1], vout[i][2], vout[i][3]);
                *reinterpret_cast<float4*>(g_u + n * H + tx * 4) = v;
                s[0] += v.x; ss[0] += v.x * v.x;
                s[1] += v.y; ss[1] += v.y * v.y;
                s[2] += v.z; ss[2] += v.z * v.z;
                s[3] += v.w; ss[3] += v.w * v.w;
            }
            __syncthreads();
            float* sRed = sA;
#pragma unroll
            for (int j = 0; j < 4; j++) {
                sRed[ty * 64 + tx * 4 + j] = s[j];
                sRed[1024 + ty * 64 + tx * 4 + j] = ss[j];
            }
            __syncthreads();
            if (tid < H) {
                float a = 0.f, b = 0.f;
#pragma unroll
                for (int r = 0; r < 16; r++) {
                    a += sRed[r * 64 + tid];
                    b += sRed[1024 + r * 64 + tid];
                }
                int bat = e0 / NS;
                atomicAdd(&g_stats[(bat * H + tid) * 2 + 0], a);
                atomicAdd(&g_stats[(bat * H + tid) * 2 + 1], b);
            }
        }
    }
}

// -------------------- InstanceNorm apply (float4) --------------------
__global__ void k_norm() {
    int idx = blockIdx.x * blockDim.x + threadIdx.x;  // NN*H/4 threads
    int n = idx >> 4;
    int c = (idx & 15) << 2;
    int b = n >> 11;
    float4 u = *(const float4*)(g_u + n * H + c);
    const float2* st = (const float2*)(g_stats + (b * H + c) * 2);
    float4 r;
    {
        float2 p = st[0];
        float mean = p.x * (1.f / NS);
        float var = p.y * (1.f / NS) - mean * mean;
        r.x = (u.x - mean) * rsqrtf(var + EPSN);
    }
    {
        float2 p = st[1];
        float mean = p.x * (1.f / NS);
        float var = p.y * (1.f / NS) - mean * mean;
        r.y = (u.y - mean) * rsqrtf(var + EPSN);
    }
    {
        float2 p = st[2];
        float mean = p.x * (1.f / NS);
        float var = p.y * (1.f / NS) - mean * mean;
        r.z = (u.z - mean) * rsqrtf(var + EPSN);
    }
    {
        float2 p = st[3];
        float mean = p.x * (1.f / NS);
        float var = p.y * (1.f / NS) - mean * mean;
        r.w = (u.w - mean) * rsqrtf(var + EPSN);
    }
    *(float4*)(g_h + n * H + c) = r;
}

// -------------------- decoder + normalize --------------------
__global__ void k_decode(const float* __restrict__ W, const float* __restrict__ b,
                         float* __restrict__ out) {
    __shared__ float sW[H * 3];
    __shared__ float sb[3];
    int tid = threadIdx.x;
    if (tid < H * 3) sW[tid] = W[tid];
    if (tid < 3) sb[tid] = b[tid];
    __syncthreads();
    int n = blockIdx.x * blockDim.x + tid;
    const float4* hr = (const float4*)(g_h + n * H);
    float a0 = sb[0], a1 = sb[1], a2 = sb[2];
#pragma unroll
    for (int k4 = 0; k4 < 16; k4++) {
        float4 v = hr[k4];
        int k = k4 * 4;
        a0 = fmaf(v.x, sW[(k + 0) * 3 + 0], a0); a1 = fmaf(v.x, sW[(k + 0) * 3 + 1], a1); a2 = fmaf(v.x, sW[(k + 0) * 3 + 2], a2);
        a0 = fmaf(v.y, sW[(k + 1) * 3 + 0], a0); a1 = fmaf(v.y, sW[(k + 1) * 3 + 1], a1); a2 = fmaf(v.y, sW[(k + 1) * 3 + 2], a2);
        a0 = fmaf(v.z, sW[(k + 2) * 3 + 0], a0); a1 = fmaf(v.z, sW[(k + 2) * 3 + 1], a1); a2 = fmaf(v.z, sW[(k + 2) * 3 + 2], a2);
        a0 = fmaf(v.w, sW[(k + 3) * 3 + 0], a0); a1 = fmaf(v.w, sW[(k + 3) * 3 + 1], a1); a2 = fmaf(v.w, sW[(k + 3) * 3 + 2], a2);
    }
    float inv = rsqrtf(a0 * a0 + a1 * a1 + a2 * a2);
    a0 *= inv; a1 *= inv; a2 *= inv;
    g_X[n * 3 + 0] = a0; g_X[n * 3 + 1] = a1; g_X[n * 3 + 2] = a2;
    out[n * 3 + 0] = a0; out[n * 3 + 1] = a1; out[n * 3 + 2] = a2;
}

// -------------------- fibonacci sphere + kYY --------------------
__global__ void k_fib_kyy() {
    __shared__ float sY[NY * 3];
    __shared__ float wsum[2];
    int i = threadIdx.x;  // 64 threads
    double phi = 3.14159265358979323846 * (3.0 - sqrt(5.0));
    double y = 1.0 - 2.0 * (double)i / 63.0;
    double r = sqrt(fmax(0.0, 1.0 - y * y));
    double th = phi * (double)i;
    float Yx = (float)(cos(th) * r), Yy = (float)y, Yz = (float)(sin(th) * r);
    sY[i * 3 + 0] = Yx; sY[i * 3 + 1] = Yy; sY[i * 3 + 2] = Yz;
    g_Y[i * 3 + 0] = Yx; g_Y[i * 3 + 1] = Yy; g_Y[i * 3 + 2] = Yz;
    __syncthreads();
    float acc = 0.f;
    for (int j = 0; j < NY; j++) {
        float d = Yx * sY[j * 3] + Yy * sY[j * 3 + 1] + Yz * sY[j * 3 + 2];
        acc += __expf(fmaf(2.f, d, -2.f));
    }
    for (int o = 16; o > 0; o >>= 1) acc += __shfl_down_sync(0xffffffffu, acc, o);
    if ((i & 31) == 0) wsum[i >> 5] = acc;
    __syncthreads();
    if (i == 0) g_acc[2] = ((double)wsum[0] + (double)wsum[1]) / (64.0 * 64.0);
}

// -------------------- kXY --------------------
__global__ void k_kxy() {
    __shared__ float sY[NY * 3];
    int tid = threadIdx.x;
    if (tid < NY * 3) sY[tid] = g_Y[tid];
    __syncthreads();
    int n = blockIdx.x * blockDim.x + tid;
    float x0 = g_X[n * 3], x1 = g_X[n * 3 + 1], x2 = g_X[n * 3 + 2];
    float acc = 0.f;
#pragma unroll 4
    for (int j = 0; j < NY; j++) {
        float d = fmaf(x0, sY[j * 3], fmaf(x1, sY[j * 3 + 1], x2 * sY[j * 3 + 2]));
        acc += __expf(fmaf(2.f, d, -2.f));
    }
    for (int o = 16; o > 0; o >>= 1) acc += __shfl_down_sync(0xffffffffu, acc, o);
    if ((tid & 31) == 0) atomicAdd(&g_acc[1], (double)acc);
}

// -------------------- kXX --------------------
__global__ void __launch_bounds__(128) k_kxx() {
    __shared__ float sx[NS], sy[NS], sz[NS];
    int b = blockIdx.x, tid = threadIdx.x;
    const float* Xb = g_X + b * NS * 3;
    for (int t = tid; t < NS; t += 128) {
        sx[t] = Xb[t * 3]; sy[t] = Xb[t * 3 + 1]; sz[t] = Xb[t * 3 + 2];
    }
    __syncthreads();
    int row = blockIdx.y * 128 + tid;
    float x0 = sx[row], x1 = sy[row], x2 = sz[row];
    float acc = 0.f;
#pragma unroll 4
    for (int j = 0; j < NS; j++) {
        float d = fmaf(x0, sx[j], fmaf(x1, sy[j], x2 * sz[j]));
        acc += __expf(fmaf(2.f, d, -2.f));
    }
    for (int o = 16; o > 0; o >>= 1) acc += __shfl_down_sync(0xffffffffu, acc, o);
    if ((tid & 31) == 0) atomicAdd(&g_acc[0], (double)acc);
}

// -------------------- finalize loss --------------------
__global__ void k_final(float* out, int writeLoss) {
    double loss = g_acc[0] / ((double)NBATCH * NS * NS)
                - 2.0 * g_acc[1] / ((double)NBATCH * NS * NY)
                + g_acc[2];
    if (writeLoss) out[0] = (float)loss;
}

// -------------------- host launch --------------------
extern "C" void kernel_launch(void* const* d_in, const int* in_sizes, int n_in,
                              void* d_out, int out_size) {
    const float* x    = (const float*)d_in[0];
    const int*   esrc = (const int*)d_in[1];
    const int*   edst = (const int*)d_in[2];
    int o = (in_sizes[3] == 1) ? 4 : 3;
    const float* encW = (const float*)d_in[o + 0];
    const float* encb = (const float*)d_in[o + 1];
    const float* m1W  = (const float*)d_in[o + 2];
    const float* m1b  = (const float*)d_in[o + 3];
    const float* m2W  = (const float*)d_in[o + 4];
    const float* m2b  = (const float*)d_in[o + 5];
    const float* u1W  = (const float*)d_in[o + 6];
    const float* u1b  = (const float*)d_in[o + 7];
    const float* u2W  = (const float*)d_in[o + 8];
    const float* u2b  = (const float*)d_in[o + 9];
    const float* decW = (const float*)d_in[o + 10];
    const float* decb = (const float*)d_in[o + 11];
    float* out = (float*)d_out;
    int base = (out_size >= NN * 3 + 1) ? 1 : 0;

    size_t SMEM = (size_t)(H2 * H + H * H + H2 * TEP + H * TEP) * sizeof(float)
                + TE * sizeof(int);
    cudaFuncSetAttribute(k_mlp<0>, cudaFuncAttributeMaxDynamicSharedMemorySize, (int)SMEM);
    cudaFuncSetAttribute(k_mlp<1>, cudaFuncAttributeMaxDynamicSharedMemorySize, (int)SMEM);

    void *p_agg, *p_stats, *p_acc;
    cudaGetSymbolAddress(&p_agg, g_agg);
    cudaGetSymbolAddress(&p_stats, g_stats);
    cudaGetSymbolAddress(&p_acc, g_acc);

    k_encode<<<NN * H / 256, 256>>>(x, encW, encb);

    for (int l = 0; l < NL; l++) {
        cudaMemsetAsync(p_agg, 0, (size_t)NN * H * sizeof(float));
        k_mlp<0><<<GRID_MLP, 256, SMEM>>>(esrc, edst,
                                          m1W + l * H2 * H, m1b + l * H,
                                          m2W + l * H * H, m2b + l * H);
        cudaMemsetAsync(p_stats, 0, (size_t)NBATCH * H * 2 * sizeof(float));
        k_mlp<1><<<GRID_MLP, 256, SMEM>>>(nullptr, nullptr,
                                          u1W + l * H2 * H, u1b + l * H,
                                          u2W + l * H * H, u2b + l * H);
        k_norm<<<NN * H / 4 / 256, 256>>>();
    }

    k_decode<<<NN / 256, 256>>>(decW, decb, out + base);

    cudaMemsetAsync(p_acc, 0, 3 * sizeof(double));
    k_fib_kyy<<<1, 64>>>();
    k_kxy<<<NN / 256, 256>>>();
    dim3 gxx(NBATCH, NS / 128);
    k_kxx<<<gxx, 128>>>();
    k_final<<<1, 1>>>(out, base);
}